// round 1
// baseline (speedup 1.0000x reference)
#include <cuda_runtime.h>
#include <math.h>

// Shapes are fixed by the problem: x, target = [B=8, C=256, H=128, W=128] fp32.
#define B_DIM   8
#define C_DIM   256
#define HW_DIM  (128 * 128)            // 16384 floats per (b,c) slab
#define N_PER_C ((double)(B_DIM * HW_DIM))  // 131072 elements reduced per channel
#define CHUNKS  (C_DIM * B_DIM)        // 2048 slabs
#define THREADS 256
#define F4_ITER (HW_DIM / (THREADS * 4))  // 16 float4 loads per thread per tensor

// Per-slab partial sums: [chunk][ sx1..sx5, sy1..sy5 ] in fp64.
// Written fully every launch -> no init needed, deterministic.
__device__ double g_partials[CHUNKS][10];

__device__ __forceinline__ float warp_red(float v) {
#pragma unroll
    for (int o = 16; o; o >>= 1) v += __shfl_xor_sync(0xffffffffu, v, o);
    return v;
}

__global__ __launch_bounds__(THREADS) void moments_kernel(
    const float* __restrict__ x, const float* __restrict__ y) {
    const int chunk = blockIdx.x;
    const int c = chunk >> 3;          // channel
    const int b = chunk & 7;           // batch slab
    const size_t base = (size_t)b * C_DIM * HW_DIM + (size_t)c * HW_DIM;
    const float4* __restrict__ x4 = (const float4*)(x + base);
    const float4* __restrict__ y4 = (const float4*)(y + base);
    const int tid = threadIdx.x;

    float sx1 = 0.f, sx2 = 0.f, sx3 = 0.f, sx4 = 0.f, sx5 = 0.f;
    float sy1 = 0.f, sy2 = 0.f, sy3 = 0.f, sy4 = 0.f, sy5 = 0.f;

#pragma unroll
    for (int i = 0; i < F4_ITER; i++) {
        float4 vx = x4[tid + i * THREADS];
        float4 vy = y4[tid + i * THREADS];
#pragma unroll
        for (int l = 0; l < 4; l++) {
            float v = (l == 0) ? vx.x : (l == 1) ? vx.y : (l == 2) ? vx.z : vx.w;
            float v2 = v * v;
            float v3 = v2 * v;
            sx1 += v;
            sx2 += v2;
            sx3 += v3;
            sx4 = fmaf(v2, v2, sx4);
            sx5 = fmaf(v3, v2, sx5);
            float w = (l == 0) ? vy.x : (l == 1) ? vy.y : (l == 2) ? vy.z : vy.w;
            float w2 = w * w;
            float w3 = w2 * w;
            sy1 += w;
            sy2 += w2;
            sy3 += w3;
            sy4 = fmaf(w2, w2, sy4);
            sy5 = fmaf(w3, w2, sy5);
        }
    }

    // Warp tree-reduce (fp32), then cross-warp in fp64.
    sx1 = warp_red(sx1); sx2 = warp_red(sx2); sx3 = warp_red(sx3);
    sx4 = warp_red(sx4); sx5 = warp_red(sx5);
    sy1 = warp_red(sy1); sy2 = warp_red(sy2); sy3 = warp_red(sy3);
    sy4 = warp_red(sy4); sy5 = warp_red(sy5);

    __shared__ double sh[THREADS / 32][10];
    const int lane = tid & 31, wid = tid >> 5;
    if (lane == 0) {
        sh[wid][0] = (double)sx1; sh[wid][1] = (double)sx2; sh[wid][2] = (double)sx3;
        sh[wid][3] = (double)sx4; sh[wid][4] = (double)sx5;
        sh[wid][5] = (double)sy1; sh[wid][6] = (double)sy2; sh[wid][7] = (double)sy3;
        sh[wid][8] = (double)sy4; sh[wid][9] = (double)sy5;
    }
    __syncthreads();
    if (tid < 10) {
        double a = 0.0;
#pragma unroll
        for (int w = 0; w < THREADS / 32; w++) a += sh[w][tid];
        g_partials[chunk][tid] = a;
    }
}

__global__ __launch_bounds__(C_DIM) void finalize_kernel(float* __restrict__ out) {
    const int c = threadIdx.x;  // one thread per channel

    double s[10];
#pragma unroll
    for (int j = 0; j < 10; j++) s[j] = 0.0;
    for (int b = 0; b < B_DIM; b++) {
#pragma unroll
        for (int j = 0; j < 10; j++) s[j] += g_partials[c * B_DIM + b][j];
    }
    const double inv = 1.0 / N_PER_C;
    double mux = s[0] * inv, r2x = s[1] * inv, r3x = s[2] * inv, r4x = s[3] * inv, r5x = s[4] * inv;
    double muy = s[5] * inv, r2y = s[6] * inv, r3y = s[7] * inv, r4y = s[8] * inv, r5y = s[9] * inv;

    double mux2 = mux * mux, muy2 = muy * muy;
    // exact binomial recovery of centered moments from raw moments
    double m2x = r2x - mux2;
    double m3x = r3x - 3.0 * mux * r2x + 2.0 * mux2 * mux;
    double m4x = r4x - 4.0 * mux * r3x + 6.0 * mux2 * r2x - 3.0 * mux2 * mux2;
    double m5x = r5x - 5.0 * mux * r4x + 10.0 * mux2 * r3x - 10.0 * mux2 * mux * r2x
               + 4.0 * mux2 * mux2 * mux;
    double m2y = r2y - muy2;
    double m3y = r3y - 3.0 * muy * r2y + 2.0 * muy2 * muy;
    double m4y = r4y - 4.0 * muy * r3y + 6.0 * muy2 * r2y - 3.0 * muy2 * muy2;
    double m5y = r5y - 5.0 * muy * r4y + 10.0 * muy2 * r3y - 10.0 * muy2 * muy * r2y
               + 4.0 * muy2 * muy2 * muy;

    double d1 = mux - muy, d2 = m2x - m2y, d3 = m3x - m3y, d4 = m4x - m4y, d5 = m5x - m5y;
    double q[5] = { d1 * d1, d2 * d2, d3 * d3, d4 * d4, d5 * d5 };

    // Block reduction over 256 channels (8 warps) for each of the 5 sums.
#pragma unroll
    for (int k = 0; k < 5; k++) {
#pragma unroll
        for (int o = 16; o; o >>= 1) q[k] += __shfl_xor_sync(0xffffffffu, q[k], o);
    }
    __shared__ double shq[8][5];
    const int lane = c & 31, wid = c >> 5;
    if (lane == 0) {
#pragma unroll
        for (int k = 0; k < 5; k++) shq[wid][k] = q[k];
    }
    __syncthreads();
    if (c == 0) {
        double tot[5] = {0, 0, 0, 0, 0};
#pragma unroll
        for (int w = 0; w < 8; w++)
#pragma unroll
            for (int k = 0; k < 5; k++) tot[k] += shq[w][k];
        double loss = sqrt(tot[0]) + sqrt(tot[1]) + sqrt(tot[2]) + sqrt(tot[3]) + sqrt(tot[4]);
        out[0] = (float)loss;
    }
}

extern "C" void kernel_launch(void* const* d_in, const int* in_sizes, int n_in,
                              void* d_out, int out_size) {
    const float* x = (const float*)d_in[0];
    const float* t = (const float*)d_in[1];
    moments_kernel<<<CHUNKS, THREADS>>>(x, t);
    finalize_kernel<<<1, C_DIM>>>((float*)d_out);
}

// round 2
// speedup vs baseline: 1.0296x; 1.0296x over previous
#include <cuda_runtime.h>
#include <math.h>

// Shapes fixed: x, target = [B=8, C=256, H=128, W=128] fp32.
#define B_DIM   8
#define C_DIM   256
#define HW_DIM  (128 * 128)                 // 16384 floats per (b,c) slab
#define N_PER_C ((double)(B_DIM * HW_DIM))  // 131072 elements per channel
#define SLABS   (B_DIM * C_DIM)             // 2048 flat slabs, slab s = b*256 + c
#define THREADS 256
#define F4_ITER (HW_DIM / (THREADS * 4))    // 16 float4 loads per thread per tensor

// Per-slab partial sums, moment-major for coalesced finalize reads:
// g_part[j][s], j = {sx1..sx5, sy1..sy5}. Written fully every launch.
__device__ float g_part[10][SLABS];

__device__ __forceinline__ float warp_red(float v) {
#pragma unroll
    for (int o = 16; o; o >>= 1) v += __shfl_xor_sync(0xffffffffu, v, o);
    return v;
}

__global__ __launch_bounds__(THREADS) void moments_kernel(
    const float* __restrict__ x, const float* __restrict__ y) {
    const int s = blockIdx.x;                       // flat slab: contiguous 64KB region
    const size_t base = (size_t)s * HW_DIM;
    const float4* __restrict__ x4 = (const float4*)(x + base);
    const float4* __restrict__ y4 = (const float4*)(y + base);
    const int tid = threadIdx.x;

    float sx1 = 0.f, sx2 = 0.f, sx3 = 0.f, sx4 = 0.f, sx5 = 0.f;
    float sy1 = 0.f, sy2 = 0.f, sy3 = 0.f, sy4 = 0.f, sy5 = 0.f;

#pragma unroll 4
    for (int i = 0; i < F4_ITER; i++) {
        float4 vx = __ldcs(&x4[tid + i * THREADS]);  // streamed: data touched once
        float4 vy = __ldcs(&y4[tid + i * THREADS]);
#pragma unroll
        for (int l = 0; l < 4; l++) {
            float v = (l == 0) ? vx.x : (l == 1) ? vx.y : (l == 2) ? vx.z : vx.w;
            float v2 = v * v;
            float v3 = v2 * v;
            sx1 += v;
            sx2 += v2;
            sx3 += v3;
            sx4 = fmaf(v2, v2, sx4);
            sx5 = fmaf(v3, v2, sx5);
            float w = (l == 0) ? vy.x : (l == 1) ? vy.y : (l == 2) ? vy.z : vy.w;
            float w2 = w * w;
            float w3 = w2 * w;
            sy1 += w;
            sy2 += w2;
            sy3 += w3;
            sy4 = fmaf(w2, w2, sy4);
            sy5 = fmaf(w3, w2, sy5);
        }
    }

    sx1 = warp_red(sx1); sx2 = warp_red(sx2); sx3 = warp_red(sx3);
    sx4 = warp_red(sx4); sx5 = warp_red(sx5);
    sy1 = warp_red(sy1); sy2 = warp_red(sy2); sy3 = warp_red(sy3);
    sy4 = warp_red(sy4); sy5 = warp_red(sy5);

    __shared__ float sh[THREADS / 32][10];
    const int lane = tid & 31, wid = tid >> 5;
    if (lane == 0) {
        sh[wid][0] = sx1; sh[wid][1] = sx2; sh[wid][2] = sx3;
        sh[wid][3] = sx4; sh[wid][4] = sx5;
        sh[wid][5] = sy1; sh[wid][6] = sy2; sh[wid][7] = sy3;
        sh[wid][8] = sy4; sh[wid][9] = sy5;
    }
    __syncthreads();
    if (tid < 10) {
        double a = 0.0;
#pragma unroll
        for (int w = 0; w < THREADS / 32; w++) a += (double)sh[w][tid];
        g_part[tid][s] = (float)a;
    }
}

__global__ __launch_bounds__(C_DIM) void finalize_kernel(float* __restrict__ out) {
    const int c = threadIdx.x;  // one thread per channel; lanes consecutive in c

    double s[10];
#pragma unroll
    for (int j = 0; j < 10; j++) s[j] = 0.0;
#pragma unroll
    for (int b = 0; b < B_DIM; b++) {
#pragma unroll
        for (int j = 0; j < 10; j++)
            s[j] += (double)g_part[j][b * C_DIM + c];  // coalesced: lane stride 4B
    }
    const double inv = 1.0 / N_PER_C;
    double mux = s[0] * inv, r2x = s[1] * inv, r3x = s[2] * inv, r4x = s[3] * inv, r5x = s[4] * inv;
    double muy = s[5] * inv, r2y = s[6] * inv, r3y = s[7] * inv, r4y = s[8] * inv, r5y = s[9] * inv;

    double mux2 = mux * mux, muy2 = muy * muy;
    // exact binomial recovery of centered moments from raw moments
    double m2x = r2x - mux2;
    double m3x = r3x - 3.0 * mux * r2x + 2.0 * mux2 * mux;
    double m4x = r4x - 4.0 * mux * r3x + 6.0 * mux2 * r2x - 3.0 * mux2 * mux2;
    double m5x = r5x - 5.0 * mux * r4x + 10.0 * mux2 * r3x - 10.0 * mux2 * mux * r2x
               + 4.0 * mux2 * mux2 * mux;
    double m2y = r2y - muy2;
    double m3y = r3y - 3.0 * muy * r2y + 2.0 * muy2 * muy;
    double m4y = r4y - 4.0 * muy * r3y + 6.0 * muy2 * r2y - 3.0 * muy2 * muy2;
    double m5y = r5y - 5.0 * muy * r4y + 10.0 * muy2 * r3y - 10.0 * muy2 * muy * r2y
               + 4.0 * muy2 * muy2 * muy;

    double d1 = mux - muy, d2 = m2x - m2y, d3 = m3x - m3y, d4 = m4x - m4y, d5 = m5x - m5y;
    double q[5] = { d1 * d1, d2 * d2, d3 * d3, d4 * d4, d5 * d5 };

#pragma unroll
    for (int k = 0; k < 5; k++) {
#pragma unroll
        for (int o = 16; o; o >>= 1) q[k] += __shfl_xor_sync(0xffffffffu, q[k], o);
    }
    __shared__ double shq[8][5];
    const int lane = c & 31, wid = c >> 5;
    if (lane == 0) {
#pragma unroll
        for (int k = 0; k < 5; k++) shq[wid][k] = q[k];
    }
    __syncthreads();
    if (c == 0) {
        double tot[5] = {0, 0, 0, 0, 0};
#pragma unroll
        for (int w = 0; w < 8; w++)
#pragma unroll
            for (int k = 0; k < 5; k++) tot[k] += shq[w][k];
        double loss = sqrt(tot[0]) + sqrt(tot[1]) + sqrt(tot[2]) + sqrt(tot[3]) + sqrt(tot[4]);
        out[0] = (float)loss;
    }
}

extern "C" void kernel_launch(void* const* d_in, const int* in_sizes, int n_in,
                              void* d_out, int out_size) {
    const float* x = (const float*)d_in[0];
    const float* t = (const float*)d_in[1];
    moments_kernel<<<SLABS, THREADS>>>(x, t);
    finalize_kernel<<<1, C_DIM>>>((float*)d_out);
}

// round 3
// speedup vs baseline: 1.4045x; 1.3641x over previous
#include <cuda_runtime.h>
#include <math.h>

// Shapes fixed: x, target = [B=8, C=256, H=128, W=128] fp32.
#define B_DIM   8
#define C_DIM   256
#define HW_DIM  (128 * 128)                 // 16384 floats per (b,c) slab
#define N_PER_C ((float)(B_DIM * HW_DIM))   // 131072 elements per channel
#define SLABS   (B_DIM * C_DIM)             // 2048 flat slabs, slab s = b*256 + c
#define THREADS 256
#define F4_ITER (HW_DIM / (THREADS * 4))    // 16 float4 loads per thread per tensor

// Per-slab partial sums, moment-major for coalesced finalize reads:
// g_part[j][s], j = {sx1..sx5, sy1..sy5}. Written fully every launch.
__device__ float g_part[10][SLABS];

__device__ __forceinline__ float warp_red(float v) {
#pragma unroll
    for (int o = 16; o; o >>= 1) v += __shfl_xor_sync(0xffffffffu, v, o);
    return v;
}

__global__ __launch_bounds__(THREADS) void moments_kernel(
    const float* __restrict__ x, const float* __restrict__ y) {
    const int s = blockIdx.x;                       // flat slab: contiguous 64KB region
    const size_t base = (size_t)s * HW_DIM;
    const float4* __restrict__ x4 = (const float4*)(x + base);
    const float4* __restrict__ y4 = (const float4*)(y + base);
    const int tid = threadIdx.x;

    float sx1 = 0.f, sx2 = 0.f, sx3 = 0.f, sx4 = 0.f, sx5 = 0.f;
    float sy1 = 0.f, sy2 = 0.f, sy3 = 0.f, sy4 = 0.f, sy5 = 0.f;

#pragma unroll 4
    for (int i = 0; i < F4_ITER; i++) {
        float4 vx = __ldcs(&x4[tid + i * THREADS]);  // streamed: data touched once
        float4 vy = __ldcs(&y4[tid + i * THREADS]);
#pragma unroll
        for (int l = 0; l < 4; l++) {
            float v = (l == 0) ? vx.x : (l == 1) ? vx.y : (l == 2) ? vx.z : vx.w;
            float v2 = v * v;
            float v3 = v2 * v;
            sx1 += v;
            sx2 += v2;
            sx3 += v3;
            sx4 = fmaf(v2, v2, sx4);
            sx5 = fmaf(v3, v2, sx5);
            float w = (l == 0) ? vy.x : (l == 1) ? vy.y : (l == 2) ? vy.z : vy.w;
            float w2 = w * w;
            float w3 = w2 * w;
            sy1 += w;
            sy2 += w2;
            sy3 += w3;
            sy4 = fmaf(w2, w2, sy4);
            sy5 = fmaf(w3, w2, sy5);
        }
    }

    sx1 = warp_red(sx1); sx2 = warp_red(sx2); sx3 = warp_red(sx3);
    sx4 = warp_red(sx4); sx5 = warp_red(sx5);
    sy1 = warp_red(sy1); sy2 = warp_red(sy2); sy3 = warp_red(sy3);
    sy4 = warp_red(sy4); sy5 = warp_red(sy5);

    __shared__ float sh[THREADS / 32][10];
    const int lane = tid & 31, wid = tid >> 5;
    if (lane == 0) {
        sh[wid][0] = sx1; sh[wid][1] = sx2; sh[wid][2] = sx3;
        sh[wid][3] = sx4; sh[wid][4] = sx5;
        sh[wid][5] = sy1; sh[wid][6] = sy2; sh[wid][7] = sy3;
        sh[wid][8] = sy4; sh[wid][9] = sy5;
    }
    __syncthreads();
    if (tid < 10) {
        float a = 0.f;
#pragma unroll
        for (int w = 0; w < THREADS / 32; w++) a += sh[w][tid];
        g_part[tid][s] = a;
    }
}

// All-fp32 finalize: B300 fp64 pipe is ~18.4 cyc/op/SM — avoiding DFMA entirely
// takes this kernel from ~24us to ~2us. Error analysis: fp32 here contributes
// <1e-6 relative to the loss (no catastrophic cancellation; corrections are
// O(sample moments)).
__global__ __launch_bounds__(C_DIM) void finalize_kernel(float* __restrict__ out) {
    const int c = threadIdx.x;  // one thread per channel; lanes consecutive in c

    float s[10];
#pragma unroll
    for (int j = 0; j < 10; j++) s[j] = 0.f;
#pragma unroll
    for (int b = 0; b < B_DIM; b++) {
#pragma unroll
        for (int j = 0; j < 10; j++)
            s[j] += g_part[j][b * C_DIM + c];  // coalesced: lane stride 4B
    }
    const float inv = 1.0f / N_PER_C;
    float mux = s[0] * inv, r2x = s[1] * inv, r3x = s[2] * inv, r4x = s[3] * inv, r5x = s[4] * inv;
    float muy = s[5] * inv, r2y = s[6] * inv, r3y = s[7] * inv, r4y = s[8] * inv, r5y = s[9] * inv;

    float mux2 = mux * mux, muy2 = muy * muy;
    // exact binomial recovery of centered moments from raw moments
    float m2x = r2x - mux2;
    float m3x = r3x - 3.f * mux * r2x + 2.f * mux2 * mux;
    float m4x = r4x - 4.f * mux * r3x + 6.f * mux2 * r2x - 3.f * mux2 * mux2;
    float m5x = r5x - 5.f * mux * r4x + 10.f * mux2 * r3x - 10.f * mux2 * mux * r2x
              + 4.f * mux2 * mux2 * mux;
    float m2y = r2y - muy2;
    float m3y = r3y - 3.f * muy * r2y + 2.f * muy2 * muy;
    float m4y = r4y - 4.f * muy * r3y + 6.f * muy2 * r2y - 3.f * muy2 * muy2;
    float m5y = r5y - 5.f * muy * r4y + 10.f * muy2 * r3y - 10.f * muy2 * muy * r2y
              + 4.f * muy2 * muy2 * muy;

    float d1 = mux - muy, d2 = m2x - m2y, d3 = m3x - m3y, d4 = m4x - m4y, d5 = m5x - m5y;
    float q[5] = { d1 * d1, d2 * d2, d3 * d3, d4 * d4, d5 * d5 };

#pragma unroll
    for (int k = 0; k < 5; k++) {
#pragma unroll
        for (int o = 16; o; o >>= 1) q[k] += __shfl_xor_sync(0xffffffffu, q[k], o);
    }
    __shared__ float shq[8][5];
    const int lane = c & 31, wid = c >> 5;
    if (lane == 0) {
#pragma unroll
        for (int k = 0; k < 5; k++) shq[wid][k] = q[k];
    }
    __syncthreads();
    if (c == 0) {
        float tot[5] = {0, 0, 0, 0, 0};
#pragma unroll
        for (int w = 0; w < 8; w++)
#pragma unroll
            for (int k = 0; k < 5; k++) tot[k] += shq[w][k];
        float loss = sqrtf(tot[0]) + sqrtf(tot[1]) + sqrtf(tot[2]) + sqrtf(tot[3]) + sqrtf(tot[4]);
        out[0] = loss;
    }
}

extern "C" void kernel_launch(void* const* d_in, const int* in_sizes, int n_in,
                              void* d_out, int out_size) {
    const float* x = (const float*)d_in[0];
    const float* t = (const float*)d_in[1];
    moments_kernel<<<SLABS, THREADS>>>(x, t);
    finalize_kernel<<<1, C_DIM>>>((float*)d_out);
}